// round 13
// baseline (speedup 1.0000x reference)
#include <cuda_runtime.h>
#include <math.h>

// ---------------------------------------------------------------------------
// GCN(2)->node0->LSTM->FC. Only the 2-hop in-neighborhood of node 0 matters:
// S1 = in-neighbors of 0 (~32), S2 = in-neighbors of S1 (~1100).
// FIVE kernels (R6 best-known bodies + validated agg/init improvements):
//   1 scan1 : dst==0            -> e0 list, S1 set, bm1
//   2 scan2 : dst in bm1 (SMEM) -> e1 list, S2 set, bm2
//   3 s3h   : dst in bm2 (SMEM) -> deg ; then hlin = x[:,u]@W1 (fused, R6)
//   4 agg   : layer-1 aggregation, ONE dependent-chain iteration per group
//   5 tail  : h2 = relu(acc1+b1)@W2 ; node-0 agg ; LSTM ; FC ; epilogue
//             resets all touched state to canonical (no init kernel needed:
//             static device initializers seed the first run).
// ---------------------------------------------------------------------------

#define NN_MAX   100000
#define IND      128
#define H        64
#define S1CAP    512
#define E0CAP    2048
#define ECAP     32768
#define BMW      ((NN_MAX + 31) / 32)   // 3125 words = 12.5 KB
#define SCAN_B   296
#define SCAN_T   512

static __device__ int      g_deg[NN_MAX];
static __device__ int      g_flag1[NN_MAX] = {1};   // node 0 seeded: pos+1
static __device__ int      g_flag2[NN_MAX] = {1};
static __device__ unsigned g_bm1[BMW] = {1u};       // bit0 = node 0
static __device__ unsigned g_bm2[BMW] = {1u};
static __device__ int      g_s1[S1CAP];             // s1[0] = 0 (node 0)
static __device__ int      g_e0[E0CAP];             // src of edges with dst==0
static __device__ int      g_s2[ECAP];              // s2[0] = 0
static __device__ int2     g_e1[ECAP];              // edges with dst in S1
static __device__ int      g_cnt1 = 1, g_cnt2 = 1, g_cntE0 = 0, g_cntE1 = 0;
static __device__ float    g_hlin[ECAP][H];
static __device__ float    g_acc1[S1CAP][H];        // zero-init; tail re-zeros
static __device__ float    g_h2[S1CAP][H];

// ---------------------------------------------------------------------------
__device__ __forceinline__ void s1_one(const int* __restrict__ src, int d, int idx) {
    if (d == 0) {
        int s = __ldcg(&src[idx]);
        int p = atomicAdd(&g_cntE0, 1);
        if (p < E0CAP) g_e0[p] = s;
        if (atomicCAS(&g_flag1[s], 0, -1) == 0) {
            int q = atomicAdd(&g_cnt1, 1);
            if (q < S1CAP) g_s1[q] = s;
            g_flag1[s] = q + 1;
            atomicOr(&g_bm1[s >> 5], 1u << (s & 31));
            if (atomicCAS(&g_flag2[s], 0, -1) == 0) {
                int r = atomicAdd(&g_cnt2, 1);
                if (r < ECAP) g_s2[r] = s;
                g_flag2[s] = r + 1;
                atomicOr(&g_bm2[s >> 5], 1u << (s & 31));
            }
        }
    }
}

__global__ void __launch_bounds__(SCAN_T)
k_scan1(const int* __restrict__ src, const int* __restrict__ dst, int E) {
    int gid = blockIdx.x * SCAN_T + threadIdx.x;
    int nth = SCAN_B * SCAN_T;
    int E4 = E >> 2;
    const int4* d4 = (const int4*)dst;
    int i = gid;
    for (; i + 3 * nth < E4; i += 4 * nth) {
        int4 v0 = __ldcg(&d4[i]);
        int4 v1 = __ldcg(&d4[i + nth]);
        int4 v2 = __ldcg(&d4[i + 2 * nth]);
        int4 v3 = __ldcg(&d4[i + 3 * nth]);
        int j;
        j = i;           s1_one(src, v0.x, 4*j); s1_one(src, v0.y, 4*j+1); s1_one(src, v0.z, 4*j+2); s1_one(src, v0.w, 4*j+3);
        j = i + nth;     s1_one(src, v1.x, 4*j); s1_one(src, v1.y, 4*j+1); s1_one(src, v1.z, 4*j+2); s1_one(src, v1.w, 4*j+3);
        j = i + 2 * nth; s1_one(src, v2.x, 4*j); s1_one(src, v2.y, 4*j+1); s1_one(src, v2.z, 4*j+2); s1_one(src, v2.w, 4*j+3);
        j = i + 3 * nth; s1_one(src, v3.x, 4*j); s1_one(src, v3.y, 4*j+1); s1_one(src, v3.z, 4*j+2); s1_one(src, v3.w, 4*j+3);
    }
    for (; i < E4; i += nth) {
        int4 v = __ldcg(&d4[i]);
        s1_one(src, v.x, 4*i); s1_one(src, v.y, 4*i+1); s1_one(src, v.z, 4*i+2); s1_one(src, v.w, 4*i+3);
    }
    for (int j = (E4 << 2) + gid; j < E; j += nth) s1_one(src, __ldcg(&dst[j]), j);
}

// ---------------------------------------------------------------------------
__device__ __forceinline__ void s2_one(const unsigned* sbm,
                                       const int* __restrict__ src, int d, int idx) {
    if ((sbm[d >> 5] >> (d & 31)) & 1u) {
        int s = __ldcg(&src[idx]);
        int p = atomicAdd(&g_cntE1, 1);
        if (p < ECAP) g_e1[p] = make_int2(s, d);
        if (atomicCAS(&g_flag2[s], 0, -1) == 0) {
            int r = atomicAdd(&g_cnt2, 1);
            if (r < ECAP) g_s2[r] = s;
            g_flag2[s] = r + 1;
            atomicOr(&g_bm2[s >> 5], 1u << (s & 31));
        }
    }
}

__global__ void __launch_bounds__(SCAN_T)
k_scan2(const int* __restrict__ src, const int* __restrict__ dst, int E) {
    __shared__ unsigned sbm[BMW];
    for (int k = threadIdx.x; k < BMW; k += SCAN_T) sbm[k] = __ldg(&g_bm1[k]);
    __syncthreads();
    int gid = blockIdx.x * SCAN_T + threadIdx.x;
    int nth = SCAN_B * SCAN_T;
    int E4 = E >> 2;
    const int4* d4 = (const int4*)dst;
    int i = gid;
    for (; i + 3 * nth < E4; i += 4 * nth) {
        int4 v0 = __ldcg(&d4[i]);
        int4 v1 = __ldcg(&d4[i + nth]);
        int4 v2 = __ldcg(&d4[i + 2 * nth]);
        int4 v3 = __ldcg(&d4[i + 3 * nth]);
        int j;
        j = i;           s2_one(sbm, src, v0.x, 4*j); s2_one(sbm, src, v0.y, 4*j+1); s2_one(sbm, src, v0.z, 4*j+2); s2_one(sbm, src, v0.w, 4*j+3);
        j = i + nth;     s2_one(sbm, src, v1.x, 4*j); s2_one(sbm, src, v1.y, 4*j+1); s2_one(sbm, src, v1.z, 4*j+2); s2_one(sbm, src, v1.w, 4*j+3);
        j = i + 2 * nth; s2_one(sbm, src, v2.x, 4*j); s2_one(sbm, src, v2.y, 4*j+1); s2_one(sbm, src, v2.z, 4*j+2); s2_one(sbm, src, v2.w, 4*j+3);
        j = i + 3 * nth; s2_one(sbm, src, v3.x, 4*j); s2_one(sbm, src, v3.y, 4*j+1); s2_one(sbm, src, v3.z, 4*j+2); s2_one(sbm, src, v3.w, 4*j+3);
    }
    for (; i < E4; i += nth) {
        int4 v = __ldcg(&d4[i]);
        s2_one(sbm, src, v.x, 4*i); s2_one(sbm, src, v.y, 4*i+1); s2_one(sbm, src, v.z, 4*i+2); s2_one(sbm, src, v.w, 4*i+3);
    }
    for (int j = (E4 << 2) + gid; j < E; j += nth) {
        int d = __ldcg(&dst[j]);
        s2_one(sbm, src, d, j);
    }
}

// ---------------------------------------------------------------------------
// Degree scan (bm2-gated) + hlin = x[:,u] @ W1 for u in S2 (fused; both
// depend only on scan2). This exact form measured 21.2us in R6.
__global__ void __launch_bounds__(SCAN_T)
k_scan3_hlin(const int* __restrict__ dst, int E,
             const float* __restrict__ x, const float* __restrict__ W1, int N) {
    __shared__ unsigned sbm[BMW];       // 12.5 KB
    __shared__ float    sW1[IND * H];   // 32 KB
    __shared__ float    sx[4][IND];     // 2 KB
    for (int k = threadIdx.x; k < BMW; k += SCAN_T) sbm[k] = __ldg(&g_bm2[k]);
    for (int k = threadIdx.x; k < IND * H; k += SCAN_T) sW1[k] = W1[k];
    __syncthreads();

    int gid = blockIdx.x * SCAN_T + threadIdx.x;
    int nth = SCAN_B * SCAN_T;
    int E4 = E >> 2;
    const int4* d4 = (const int4*)dst;
    int i = gid;
    for (; i + 3 * nth < E4; i += 4 * nth) {
        int4 v0 = __ldcg(&d4[i]);
        int4 v1 = __ldcg(&d4[i + nth]);
        int4 v2 = __ldcg(&d4[i + 2 * nth]);
        int4 v3 = __ldcg(&d4[i + 3 * nth]);
        #define S3(dd) if ((sbm[(dd) >> 5] >> ((dd) & 31)) & 1u) atomicAdd(&g_deg[dd], 1)
        S3(v0.x); S3(v0.y); S3(v0.z); S3(v0.w);
        S3(v1.x); S3(v1.y); S3(v1.z); S3(v1.w);
        S3(v2.x); S3(v2.y); S3(v2.z); S3(v2.w);
        S3(v3.x); S3(v3.y); S3(v3.z); S3(v3.w);
    }
    for (; i < E4; i += nth) {
        int4 v = __ldcg(&d4[i]);
        S3(v.x); S3(v.y); S3(v.z); S3(v.w);
    }
    for (int j = (E4 << 2) + gid; j < E; j += nth) { int dd = __ldcg(&dst[j]); S3(dd); }
    #undef S3

    // hlin part: 4 nodes per block (296 blocks x 4 = 1184 >= m2 -> 1 stage).
    __syncthreads();
    int m2 = g_cnt2; if (m2 > ECAP) m2 = ECAP;
    int g  = threadIdx.x >> 7;
    int lt = threadIdx.x & 127;
    for (int base = blockIdx.x * 4; base < m2; base += SCAN_B * 4) {
        int j = base + g;
        int u = (j < m2) ? g_s2[j] : -1;
        if (u >= 0) sx[g][lt] = __ldg(&x[(size_t)lt * N + u]);
        __syncthreads();
        if (u >= 0 && lt < H) {
            float acc = 0.0f;
            #pragma unroll
            for (int d = 0; d < IND; d++) acc += sx[g][d] * sW1[d * H + lt];
            g_hlin[j][lt] = acc;
        }
        __syncthreads();
    }
}

// ---------------------------------------------------------------------------
// Layer-1 aggregation: self loops + edges in ONE index space over 1184
// groups of 64 threads -> a single dependent-chain iteration per group,
// all metadata loads issued concurrently via __ldg.
__global__ void __launch_bounds__(256)
k_agg(void) {
    int tt      = threadIdx.x & 63;
    int group   = blockIdx.x * 4 + (threadIdx.x >> 6);
    int ngroups = gridDim.x * 4;
    int m1 = g_cnt1; if (m1 > S1CAP) m1 = S1CAP;
    int mE = g_cntE1; if (mE > ECAP) mE = ECAP;
    int total = m1 + mE;
    for (int t = group; t < total; t += ngroups) {
        if (t < m1) {
            int u  = __ldg(&g_s1[t]);
            float di = rsqrtf((float)__ldg(&g_deg[u]) + 1.0f);
            int p2 = __ldg(&g_flag2[u]) - 1;
            atomicAdd(&g_acc1[t][tt], di * di * __ldg(&g_hlin[p2][tt]));
        } else {
            int e = t - m1;
            int2 ed = __ldg(&g_e1[e]);
            int dp = __ldg(&g_flag1[ed.y]) - 1;
            int sp = __ldg(&g_flag2[ed.x]) - 1;
            float nrm = rsqrtf((float)__ldg(&g_deg[ed.x]) + 1.0f)
                      * rsqrtf((float)__ldg(&g_deg[ed.y]) + 1.0f);
            atomicAdd(&g_acc1[dp][tt], nrm * __ldg(&g_hlin[sp][tt]));
        }
    }
}

// ---------------------------------------------------------------------------
// Tail: h2 for S1 nodes, node-0 layer-2 agg, LSTM, FC -> out.
// EPILOGUE: restore canonical state so the next graph replay starts from
// the identical seeded state (mechanism validated in R12).
__global__ void __launch_bounds__(512)
k_tail(const float* __restrict__ b1, const float* __restrict__ W2,
       const float* __restrict__ b2, const float* __restrict__ w_ih,
       const float* __restrict__ b_ih, const float* __restrict__ b_hh,
       const float* __restrict__ fc_w, const float* __restrict__ fc_b,
       float* __restrict__ out) {
    __shared__ float sW2[H * H];        // 16 KB
    __shared__ float h1buf[8][H];       // 2 KB
    __shared__ float z[H], gates[4 * H], red[H];
    __shared__ float scof[256];
    __shared__ int   sspb[256];

    int tid = threadIdx.x;
    for (int k = tid; k < H * H; k += 512) sW2[k] = W2[k];
    __syncthreads();

    int m1 = g_cnt1; if (m1 > S1CAP) m1 = S1CAP;
    int m2 = g_cnt2; if (m2 > ECAP)  m2 = ECAP;
    int sub = tid >> 6, tt = tid & 63;
    for (int j0 = 0; j0 < m1; j0 += 8) {
        int j = j0 + sub;
        if (j < m1) h1buf[sub][tt] = fmaxf(g_acc1[j][tt] + b1[tt], 0.0f);
        __syncthreads();
        if (j < m1) {
            float acc = 0.0f;
            #pragma unroll
            for (int h = 0; h < H; h++) acc += h1buf[sub][h] * sW2[h * H + tt];
            g_h2[j][tt] = acc;
        }
        __syncthreads();
    }

    // node-0 layer-2 aggregation
    int m0 = g_cntE0; if (m0 > E0CAP) m0 = E0CAP;
    float d0 = rsqrtf((float)g_deg[0] + 1.0f);
    float zv = 0.0f;
    if (tid < H) zv = b2[tid] + d0 * d0 * g_h2[0][tid];
    for (int base = 0; base < m0; base += 256) {
        int k = base + tid;
        if (tid < 256 && k < m0) {
            int s = g_e0[k];
            scof[tid] = rsqrtf((float)g_deg[s] + 1.0f) * d0;
            sspb[tid] = g_flag1[s] - 1;
        }
        __syncthreads();
        int lim = m0 - base; if (lim > 256) lim = 256;
        if (tid < H)
            for (int e = 0; e < lim; e++) zv += scof[e] * g_h2[sspb[e]][tid];
        __syncthreads();
    }
    if (tid < H) z[tid] = zv;
    __syncthreads();

    if (tid < 4 * H) {
        float a = b_ih[tid] + b_hh[tid];
        #pragma unroll
        for (int h = 0; h < H; h++) a += __ldg(&w_ih[tid * H + h]) * z[h];
        gates[tid] = a;
    }
    __syncthreads();
    if (tid < H) {
        float ig = gates[tid];
        float gg = gates[2 * H + tid];
        float og = gates[3 * H + tid];
        float si = 1.0f / (1.0f + expf(-ig));
        float c  = si * tanhf(gg);
        float so = 1.0f / (1.0f + expf(-og));
        float hy = so * tanhf(c);
        red[tid] = hy * fc_w[tid];
    }
    __syncthreads();
    if (tid == 0) {
        float s = 0.0f;
        for (int k = 0; k < H; k++) s += red[k];
        out[0] = s + fc_b[0];
    }

    // ---------------- epilogue: reset to canonical state ----------------
    __syncthreads();   // all reads of g_* above are complete
    for (int j = 1 + tid; j < m1; j += 512) {
        int u = g_s1[j];
        g_flag1[u] = 0;
        atomicAnd(&g_bm1[u >> 5], ~(1u << (u & 31)));
    }
    for (int j = 1 + tid; j < m2; j += 512) {
        int u = g_s2[j];
        g_flag2[u] = 0;
        g_deg[u]   = 0;
        atomicAnd(&g_bm2[u >> 5], ~(1u << (u & 31)));
    }
    for (int k = tid; k < m1 * H; k += 512) ((float*)g_acc1)[k] = 0.0f;
    __syncthreads();
    if (tid == 0) {
        g_cnt1 = 1; g_cnt2 = 1; g_cntE0 = 0; g_cntE1 = 0;
        g_s1[0] = 0; g_s2[0] = 0;
        g_flag1[0] = 1; g_flag2[0] = 1;
        g_deg[0] = 0;
        atomicOr(&g_bm1[0], 1u);
        atomicOr(&g_bm2[0], 1u);
    }
}

// ---------------------------------------------------------------------------
extern "C" void kernel_launch(void* const* d_in, const int* in_sizes, int n_in,
                              void* d_out, int out_size) {
    const float* x    = (const float*)d_in[0];
    const int*   ei   = (const int*)d_in[1];
    const float* W1   = (const float*)d_in[2];
    const float* b1   = (const float*)d_in[3];
    const float* W2   = (const float*)d_in[4];
    const float* b2   = (const float*)d_in[5];
    const float* w_ih = (const float*)d_in[6];
    // d_in[7] = w_hh (unused: h0 = c0 = 0)
    const float* b_ih = (const float*)d_in[8];
    const float* b_hh = (const float*)d_in[9];
    const float* fc_w = (const float*)d_in[10];
    const float* fc_b = (const float*)d_in[11];
    float* out = (float*)d_out;

    int N = in_sizes[0] / IND;
    int E = in_sizes[1] / 2;
    const int* src = ei;
    const int* dst = ei + E;

    k_scan1<<<SCAN_B, SCAN_T>>>(src, dst, E);
    k_scan2<<<SCAN_B, SCAN_T>>>(src, dst, E);
    k_scan3_hlin<<<SCAN_B, SCAN_T>>>(dst, E, x, W1, N);
    k_agg<<<SCAN_B, 256>>>();
    k_tail<<<1, 512>>>(b1, W2, b2, w_ih, b_ih, b_hh, fc_w, fc_b, out);
}

// round 14
// speedup vs baseline: 1.2976x; 1.2976x over previous
#include <cuda_runtime.h>
#include <math.h>

// ---------------------------------------------------------------------------
// GCN(2)->node0->LSTM->FC. Only the 2-hop in-neighborhood of node 0 matters:
// S1 = in-neighbors of 0 (~32). Layer-1 inputs of S1 = sources of edges into
// S1 (~1100 rows of x@W1) -- computed ON THE FLY inside the aggregation.
// FIVE kernels, TWO edge passes (was three), no standalone hlin:
//   1 init     : zero deg histogram/flags/bm1/acc1, seed node 0
//   2 scan1deg : FULL in-degree histogram (unconditional atomics) + dst==0
//                detection -> e0 list, S1 set, bm1.   (replaces scan1+scan3)
//   3 scan2    : dst in bm1 (SMEM) -> e1 edge list only (no S2 bookkeeping)
//   4 agg      : per task (S1 self-loop or e1 edge): gather x[:,src], dot
//                with smem W1, scale by GCN norm, atomicAdd into acc1.
//                (replaces hlin + old agg; x rows touched exactly once)
//   5 tail     : one block: h2 = relu(acc1+b1)@W2 ; node-0 layer-2 agg ;
//                LSTM single step ; FC -> out
// ---------------------------------------------------------------------------

#define NN_MAX   100000
#define IND      128
#define H        64
#define S1CAP    512
#define E0CAP    2048
#define ECAP     32768
#define BMW      ((NN_MAX + 31) / 32)   // 3125 words = 12.5 KB
#define SCAN_B   296
#define SCAN_T   512

static __device__ int      g_deg[NN_MAX];     // FULL in-degree histogram
static __device__ int      g_flag1[NN_MAX];   // pos+1 in S1 (0 = not member)
static __device__ unsigned g_bm1[BMW];
static __device__ int      g_s1[S1CAP];
static __device__ int      g_e0[E0CAP];       // src of edges with dst==0
static __device__ int2     g_e1[ECAP];        // edges with dst in S1
static __device__ int      g_cnt1, g_cntE0, g_cntE1;
static __device__ float    g_acc1[S1CAP][H];
static __device__ float    g_h2[S1CAP][H];

// ---------------------------------------------------------------------------
__global__ void k_init(int N) {
    int i = blockIdx.x * blockDim.x + threadIdx.x;
    int nth = gridDim.x * blockDim.x;
    for (int k = i; k < N; k += nth) { g_deg[k] = 0; g_flag1[k] = 0; }
    for (int k = i; k < BMW; k += nth) g_bm1[k] = 0u;
    for (int k = i; k < S1CAP * H; k += nth) ((float*)g_acc1)[k] = 0.0f;
    if (i == 0) {
        g_cnt1 = 1; g_cntE0 = 0; g_cntE1 = 0;
        g_s1[0] = 0;
        g_flag1[0] = 1;
        g_bm1[0] = 1u;
    }
}

// ---------------------------------------------------------------------------
// scan1 + degree histogram fused: every edge bumps deg[dst]; dst==0 edges
// additionally build e0 / S1 / bm1.
__device__ __forceinline__ void s1d_one(const int* __restrict__ src, int d, int idx) {
    atomicAdd(&g_deg[d], 1);
    if (d == 0) {
        int s = __ldcg(&src[idx]);
        int p = atomicAdd(&g_cntE0, 1);
        if (p < E0CAP) g_e0[p] = s;
        if (atomicCAS(&g_flag1[s], 0, -1) == 0) {
            int q = atomicAdd(&g_cnt1, 1);
            if (q < S1CAP) g_s1[q] = s;
            g_flag1[s] = q + 1;
            atomicOr(&g_bm1[s >> 5], 1u << (s & 31));
        }
    }
}

__global__ void __launch_bounds__(SCAN_T)
k_scan1deg(const int* __restrict__ src, const int* __restrict__ dst, int E) {
    int gid = blockIdx.x * SCAN_T + threadIdx.x;
    int nth = SCAN_B * SCAN_T;
    int E4 = E >> 2;
    const int4* d4 = (const int4*)dst;
    int i = gid;
    for (; i + 3 * nth < E4; i += 4 * nth) {
        int4 v0 = __ldcg(&d4[i]);
        int4 v1 = __ldcg(&d4[i + nth]);
        int4 v2 = __ldcg(&d4[i + 2 * nth]);
        int4 v3 = __ldcg(&d4[i + 3 * nth]);
        int j;
        j = i;           s1d_one(src, v0.x, 4*j); s1d_one(src, v0.y, 4*j+1); s1d_one(src, v0.z, 4*j+2); s1d_one(src, v0.w, 4*j+3);
        j = i + nth;     s1d_one(src, v1.x, 4*j); s1d_one(src, v1.y, 4*j+1); s1d_one(src, v1.z, 4*j+2); s1d_one(src, v1.w, 4*j+3);
        j = i + 2 * nth; s1d_one(src, v2.x, 4*j); s1d_one(src, v2.y, 4*j+1); s1d_one(src, v2.z, 4*j+2); s1d_one(src, v2.w, 4*j+3);
        j = i + 3 * nth; s1d_one(src, v3.x, 4*j); s1d_one(src, v3.y, 4*j+1); s1d_one(src, v3.z, 4*j+2); s1d_one(src, v3.w, 4*j+3);
    }
    for (; i < E4; i += nth) {
        int4 v = __ldcg(&d4[i]);
        s1d_one(src, v.x, 4*i); s1d_one(src, v.y, 4*i+1); s1d_one(src, v.z, 4*i+2); s1d_one(src, v.w, 4*i+3);
    }
    for (int j = (E4 << 2) + gid; j < E; j += nth) s1d_one(src, __ldcg(&dst[j]), j);
}

// ---------------------------------------------------------------------------
// scan2: dst in bm1 (SMEM) -> append (src,dst) to e1. Nothing else.
__device__ __forceinline__ void s2_one(const unsigned* sbm,
                                       const int* __restrict__ src, int d, int idx) {
    if ((sbm[d >> 5] >> (d & 31)) & 1u) {
        int s = __ldcg(&src[idx]);
        int p = atomicAdd(&g_cntE1, 1);
        if (p < ECAP) g_e1[p] = make_int2(s, d);
    }
}

__global__ void __launch_bounds__(SCAN_T)
k_scan2(const int* __restrict__ src, const int* __restrict__ dst, int E) {
    __shared__ unsigned sbm[BMW];
    for (int k = threadIdx.x; k < BMW; k += SCAN_T) sbm[k] = __ldg(&g_bm1[k]);
    __syncthreads();
    int gid = blockIdx.x * SCAN_T + threadIdx.x;
    int nth = SCAN_B * SCAN_T;
    int E4 = E >> 2;
    const int4* d4 = (const int4*)dst;
    int i = gid;
    for (; i + 3 * nth < E4; i += 4 * nth) {
        int4 v0 = __ldcg(&d4[i]);
        int4 v1 = __ldcg(&d4[i + nth]);
        int4 v2 = __ldcg(&d4[i + 2 * nth]);
        int4 v3 = __ldcg(&d4[i + 3 * nth]);
        int j;
        j = i;           s2_one(sbm, src, v0.x, 4*j); s2_one(sbm, src, v0.y, 4*j+1); s2_one(sbm, src, v0.z, 4*j+2); s2_one(sbm, src, v0.w, 4*j+3);
        j = i + nth;     s2_one(sbm, src, v1.x, 4*j); s2_one(sbm, src, v1.y, 4*j+1); s2_one(sbm, src, v1.z, 4*j+2); s2_one(sbm, src, v1.w, 4*j+3);
        j = i + 2 * nth; s2_one(sbm, src, v2.x, 4*j); s2_one(sbm, src, v2.y, 4*j+1); s2_one(sbm, src, v2.z, 4*j+2); s2_one(sbm, src, v2.w, 4*j+3);
        j = i + 3 * nth; s2_one(sbm, src, v3.x, 4*j); s2_one(sbm, src, v3.y, 4*j+1); s2_one(sbm, src, v3.z, 4*j+2); s2_one(sbm, src, v3.w, 4*j+3);
    }
    for (; i < E4; i += nth) {
        int4 v = __ldcg(&d4[i]);
        s2_one(sbm, src, v.x, 4*i); s2_one(sbm, src, v.y, 4*i+1); s2_one(sbm, src, v.z, 4*i+2); s2_one(sbm, src, v.w, 4*i+3);
    }
    for (int j = (E4 << 2) + gid; j < E; j += nth) {
        int d = __ldcg(&dst[j]);
        s2_one(sbm, src, d, j);
    }
}

// ---------------------------------------------------------------------------
// Fused aggregation: tasks = [m1 self-loops | mE edges]. Each 64-thread
// group stages x[:,u] (2 scattered loads/thread), dots against smem W1,
// scales by the GCN norm and accumulates into acc1[dp]. Uniform loop trip
// count across the block keeps __syncthreads convergent.
__global__ void __launch_bounds__(256)
k_agg(const float* __restrict__ x, const float* __restrict__ W1, int N) {
    __shared__ float sW1[IND * H];     // 32 KB
    __shared__ float sx[4][IND];       // 2 KB
    int tid = threadIdx.x;
    for (int k = tid; k < IND * H; k += 256) sW1[k] = W1[k];

    int g  = tid >> 6;                  // group 0..3
    int lt = tid & 63;
    int ngroups = gridDim.x * 4;
    int m1 = g_cnt1; if (m1 > S1CAP) m1 = S1CAP;
    int mE = g_cntE1; if (mE > ECAP) mE = ECAP;
    int total = m1 + mE;
    int iters = (total + ngroups - 1) / ngroups;
    __syncthreads();

    for (int it = 0; it < iters; it++) {
        int t = blockIdx.x * 4 + g + it * ngroups;
        int u = -1, dp = 0;
        float w = 0.0f;
        if (t < total) {
            if (t < m1) {
                u  = __ldg(&g_s1[t]);
                dp = t;
                float di = rsqrtf((float)__ldg(&g_deg[u]) + 1.0f);
                w = di * di;
            } else {
                int2 ed = __ldg(&g_e1[t - m1]);
                u  = ed.x;
                dp = __ldg(&g_flag1[ed.y]) - 1;
                w = rsqrtf((float)__ldg(&g_deg[ed.x]) + 1.0f)
                  * rsqrtf((float)__ldg(&g_deg[ed.y]) + 1.0f);
            }
            // stage x[:,u]: 128 scattered loads by 64 threads (2 each)
            sx[g][lt]      = __ldg(&x[(size_t)lt * N + u]);
            sx[g][lt + 64] = __ldg(&x[(size_t)(lt + 64) * N + u]);
        }
        __syncthreads();
        if (t < total) {
            float acc = 0.0f;
            #pragma unroll
            for (int d = 0; d < IND; d++) acc += sx[g][d] * sW1[d * H + lt];
            atomicAdd(&g_acc1[dp][lt], w * acc);
        }
        __syncthreads();
    }
}

// ---------------------------------------------------------------------------
// Single block: h2 for all S1 nodes, node-0 layer-2 aggregation, LSTM, FC.
__global__ void __launch_bounds__(512)
k_tail(const float* __restrict__ b1, const float* __restrict__ W2,
       const float* __restrict__ b2, const float* __restrict__ w_ih,
       const float* __restrict__ b_ih, const float* __restrict__ b_hh,
       const float* __restrict__ fc_w, const float* __restrict__ fc_b,
       float* __restrict__ out) {
    __shared__ float sW2[H * H];        // 16 KB
    __shared__ float h1buf[8][H];       // 2 KB
    __shared__ float z[H], gates[4 * H], red[H];
    __shared__ float scof[256];
    __shared__ int   sspb[256];

    int tid = threadIdx.x;
    for (int k = tid; k < H * H; k += 512) sW2[k] = W2[k];
    __syncthreads();

    int m1 = g_cnt1; if (m1 > S1CAP) m1 = S1CAP;
    int sub = tid >> 6, tt = tid & 63;
    for (int j0 = 0; j0 < m1; j0 += 8) {
        int j = j0 + sub;
        if (j < m1) h1buf[sub][tt] = fmaxf(g_acc1[j][tt] + b1[tt], 0.0f);
        __syncthreads();
        if (j < m1) {
            float acc = 0.0f;
            #pragma unroll
            for (int h = 0; h < H; h++) acc += h1buf[sub][h] * sW2[h * H + tt];
            g_h2[j][tt] = acc;
        }
        __syncthreads();
    }

    // node-0 layer-2 aggregation
    int m0 = g_cntE0; if (m0 > E0CAP) m0 = E0CAP;
    float d0 = rsqrtf((float)g_deg[0] + 1.0f);
    float zv = 0.0f;
    if (tid < H) zv = b2[tid] + d0 * d0 * g_h2[0][tid];
    for (int base = 0; base < m0; base += 256) {
        int k = base + tid;
        if (tid < 256 && k < m0) {
            int s = g_e0[k];
            scof[tid] = rsqrtf((float)g_deg[s] + 1.0f) * d0;
            sspb[tid] = g_flag1[s] - 1;
        }
        __syncthreads();
        int lim = m0 - base; if (lim > 256) lim = 256;
        if (tid < H)
            for (int e = 0; e < lim; e++) zv += scof[e] * g_h2[sspb[e]][tid];
        __syncthreads();
    }
    if (tid < H) z[tid] = zv;
    __syncthreads();

    if (tid < 4 * H) {
        float a = b_ih[tid] + b_hh[tid];
        #pragma unroll
        for (int h = 0; h < H; h++) a += __ldg(&w_ih[tid * H + h]) * z[h];
        gates[tid] = a;
    }
    __syncthreads();
    if (tid < H) {
        float ig = gates[tid];
        float gg = gates[2 * H + tid];
        float og = gates[3 * H + tid];
        float si = 1.0f / (1.0f + expf(-ig));
        float c  = si * tanhf(gg);
        float so = 1.0f / (1.0f + expf(-og));
        float hy = so * tanhf(c);
        red[tid] = hy * fc_w[tid];
    }
    __syncthreads();
    if (tid == 0) {
        float s = 0.0f;
        for (int k = 0; k < H; k++) s += red[k];
        out[0] = s + fc_b[0];
    }
}

// ---------------------------------------------------------------------------
extern "C" void kernel_launch(void* const* d_in, const int* in_sizes, int n_in,
                              void* d_out, int out_size) {
    const float* x    = (const float*)d_in[0];
    const int*   ei   = (const int*)d_in[1];
    const float* W1   = (const float*)d_in[2];
    const float* b1   = (const float*)d_in[3];
    const float* W2   = (const float*)d_in[4];
    const float* b2   = (const float*)d_in[5];
    const float* w_ih = (const float*)d_in[6];
    // d_in[7] = w_hh (unused: h0 = c0 = 0)
    const float* b_ih = (const float*)d_in[8];
    const float* b_hh = (const float*)d_in[9];
    const float* fc_w = (const float*)d_in[10];
    const float* fc_b = (const float*)d_in[11];
    float* out = (float*)d_out;

    int N = in_sizes[0] / IND;
    int E = in_sizes[1] / 2;
    const int* src = ei;
    const int* dst = ei + E;

    k_init<<<200, 512>>>(N);
    k_scan1deg<<<SCAN_B, SCAN_T>>>(src, dst, E);
    k_scan2<<<SCAN_B, SCAN_T>>>(src, dst, E);
    k_agg<<<SCAN_B, 256>>>(x, W1, N);
    k_tail<<<1, 512>>>(b1, W2, b2, w_ih, b_ih, b_hh, fc_w, fc_b, out);
}